// round 16
// baseline (speedup 1.0000x reference)
#include <cuda_runtime.h>

// Gaussian 3D covariance: cov = (R*diag(exp(ls))) @ R^T per point.
// N=4M, HBM-streaming, plateaued at ~36.5us kernel / ~5.4TB/s.
// R16: test the DRAM read/write-turnaround hypothesis directly:
// 4 pts/thread, 36KB smem-staged output tile -> 4x longer same-
// direction write bursts per block. TPB=256, PPB=1024 (N not
// divisible -> one predicated tail block).

constexpr int TPB = 256;
constexpr int PPT = 4;
constexpr int PPB = TPB * PPT;   // 1024

__device__ __forceinline__ void compute_cov(const float4 q4,
                                            const float lsx, const float lsy, const float lsz,
                                            float* __restrict__ p) {
    const float sx = __expf(lsx);
    const float sy = __expf(lsy);
    const float sz = __expf(lsz);

    const float d   = q4.x * q4.x + q4.y * q4.y + q4.z * q4.z + q4.w * q4.w;
    const float inv = rsqrtf(fmaxf(d, 1e-24f));
    const float qw = q4.x * inv, qx = q4.y * inv, qy = q4.z * inv, qz = q4.w * inv;

    const float r00 = 1.f - 2.f * (qy * qy + qz * qz);
    const float r01 = 2.f * (qx * qy - qz * qw);
    const float r02 = 2.f * (qx * qz + qy * qw);
    const float r10 = 2.f * (qx * qy + qz * qw);
    const float r11 = 1.f - 2.f * (qx * qx + qz * qz);
    const float r12 = 2.f * (qy * qz - qx * qw);
    const float r20 = 2.f * (qx * qz - qy * qw);
    const float r21 = 2.f * (qy * qz + qx * qw);
    const float r22 = 1.f - 2.f * (qx * qx + qy * qy);

    const float a0 = r00 * sx, a1 = r01 * sy, a2 = r02 * sz;
    const float b0 = r10 * sx, b1 = r11 * sy, b2 = r12 * sz;
    const float c0 = r20 * sx, c1 = r21 * sy, c2 = r22 * sz;

    p[0] = a0 * r00 + a1 * r01 + a2 * r02;
    p[1] = a0 * r10 + a1 * r11 + a2 * r12;
    p[2] = a0 * r20 + a1 * r21 + a2 * r22;
    p[3] = b0 * r00 + b1 * r01 + b2 * r02;
    p[4] = b0 * r10 + b1 * r11 + b2 * r12;
    p[5] = b0 * r20 + b1 * r21 + b2 * r22;
    p[6] = c0 * r00 + c1 * r01 + c2 * r02;
    p[7] = c0 * r10 + c1 * r11 + c2 * r12;
    p[8] = c0 * r20 + c1 * r21 + c2 * r22;
}

__global__ __launch_bounds__(TPB) void cov_kernel(
    const float4* __restrict__ quat,   // [n] as float4 (w,x,y,z)
    const float*  __restrict__ ls,     // [n*3]
    float*        __restrict__ out,    // [n*9]
    int n)
{
    __shared__ __align__(16) float sbuf[PPB * 9];   // 36864 B

    const int base = blockIdx.x * PPB;
    const int t    = threadIdx.x;

    // Front-batch all 16 global loads (4 points, strided by TPB: coalesced).
    float4 q[PPT];
    float  l[PPT][3];
    bool   v[PPT];
    #pragma unroll
    for (int k = 0; k < PPT; k++) {
        const int i = base + k * TPB + t;
        v[k] = i < n;
        if (v[k]) {
            q[k]    = quat[i];
            l[k][0] = ls[3 * i + 0];
            l[k][1] = ls[3 * i + 1];
            l[k][2] = ls[3 * i + 2];
        }
    }

    #pragma unroll
    for (int k = 0; k < PPT; k++)
        if (v[k])
            compute_cov(q[k], l[k][0], l[k][1], l[k][2],
                        &sbuf[(k * TPB + t) * 9]);
    __syncthreads();

    // Long coalesced flush: 36KB = 2304 float4s per full block.
    const int blockPts = min(PPB, n - base);
    const long long ob = (long long)base * 9;
    if (blockPts == PPB) {
        float4*       o4 = reinterpret_cast<float4*>(out + ob);
        const float4* s4 = reinterpret_cast<const float4*>(sbuf);
        #pragma unroll
        for (int j = t; j < PPB * 9 / 4; j += TPB)
            o4[j] = s4[j];
    } else {
        const int totalFloats = blockPts * 9;
        for (int j = t; j < totalFloats; j += TPB)
            out[ob + j] = sbuf[j];
    }
}

extern "C" void kernel_launch(void* const* d_in, const int* in_sizes, int n_in,
                              void* d_out, int out_size) {
    const float4* quat = (const float4*)d_in[0];  // [N,4] float32
    const float*  ls   = (const float*)d_in[1];   // [N,3] float32
    float*        out  = (float*)d_out;           // [N,3,3] float32

    const int n = in_sizes[0] / 4;                // 4,000,000
    const int blocks = (n + PPB - 1) / PPB;       // 3907 (last one partial)
    cov_kernel<<<blocks, TPB>>>(quat, ls, out, n);
}

// round 17
// speedup vs baseline: 1.0903x; 1.0903x over previous
#include <cuda_runtime.h>

// Gaussian 3D covariance: cov = (R*diag(exp(ls))) @ R^T per point.
// N=4M, pure HBM streaming. FINAL kernel (16 rounds, exhaustive).
//
// Roofline: 256 MB irreducible traffic (112 read + 144 write). Kernel
// 36.3-37.8us across five identical-source runs; DRAM 67-70% active
// (5.3-5.5 TB/s) with ~58 MB of reads absorbed by L2 across graph
// replays = ~7 TB/s logical, ~87% of 8 TB/s spec.
//
// Falsified levers (all within or below the noise band):
//   - PPT 2 (R2, neutral), PPT 4 / 36KB bursts (R16, REGRESSED: occ 57%)
//   - TMA cp.async.bulk store (R3, neutral)
//   - L2 createpolicy evict_last loads / evict_first stores (R5/R7, neutral)
//   - .cs streaming hints (neutral-to-worse than default write-back)
//   - persistent grid + register prefetch (R6, REGRESSED: barrier-bound)
//   - v8.f32 256-bit ld/st (R8, neutral)
//   - TPB 128/512 (neutral / invalid: 512 does not divide N)
// Conclusion: mixed-stream DRAM controller ceiling; occupancy-hungry,
// footprint-light shape wins.
//
// Config: TPB=256 (N = 2^8*5^6), 1 pt/thread, default cache policy,
// smem-staged coalesced float4 flush, zero predication. regs=31, occ ~88%.

constexpr int TPB = 256;

__global__ __launch_bounds__(TPB) void cov_kernel(
    const float4* __restrict__ quat,   // [n] as float4 (w,x,y,z)
    const float*  __restrict__ ls,     // [n*3]
    float*        __restrict__ out)    // [n*9]
{
    __shared__ __align__(16) float sbuf[TPB * 9];

    const int i = blockIdx.x * TPB + threadIdx.x;

    const float4 q4 = quat[i];
    const float sx = __expf(ls[3 * i + 0]);
    const float sy = __expf(ls[3 * i + 1]);
    const float sz = __expf(ls[3 * i + 2]);

    const float d   = q4.x * q4.x + q4.y * q4.y + q4.z * q4.z + q4.w * q4.w;
    const float inv = rsqrtf(fmaxf(d, 1e-24f));
    const float qw = q4.x * inv;
    const float qx = q4.y * inv;
    const float qy = q4.z * inv;
    const float qz = q4.w * inv;

    const float r00 = 1.f - 2.f * (qy * qy + qz * qz);
    const float r01 = 2.f * (qx * qy - qz * qw);
    const float r02 = 2.f * (qx * qz + qy * qw);
    const float r10 = 2.f * (qx * qy + qz * qw);
    const float r11 = 1.f - 2.f * (qx * qx + qz * qz);
    const float r12 = 2.f * (qy * qz - qx * qw);
    const float r20 = 2.f * (qx * qz - qy * qw);
    const float r21 = 2.f * (qy * qz + qx * qw);
    const float r22 = 1.f - 2.f * (qx * qx + qy * qy);

    const float a0 = r00 * sx, a1 = r01 * sy, a2 = r02 * sz;
    const float b0 = r10 * sx, b1 = r11 * sy, b2 = r12 * sz;
    const float c0 = r20 * sx, c1 = r21 * sy, c2 = r22 * sz;

    float* p = &sbuf[threadIdx.x * 9];
    p[0] = a0 * r00 + a1 * r01 + a2 * r02;
    p[1] = a0 * r10 + a1 * r11 + a2 * r12;
    p[2] = a0 * r20 + a1 * r21 + a2 * r22;
    p[3] = b0 * r00 + b1 * r01 + b2 * r02;
    p[4] = b0 * r10 + b1 * r11 + b2 * r12;
    p[5] = b0 * r20 + b1 * r21 + b2 * r22;
    p[6] = c0 * r00 + c1 * r01 + c2 * r02;
    p[7] = c0 * r10 + c1 * r11 + c2 * r12;
    p[8] = c0 * r20 + c1 * r21 + c2 * r22;

    __syncthreads();

    // Coalesced full-block flush: 2304 floats = 576 float4s, default policy.
    float4*       o4 = reinterpret_cast<float4*>(out + (long long)blockIdx.x * (TPB * 9));
    const float4* s4 = reinterpret_cast<const float4*>(sbuf);
    #pragma unroll
    for (int j = threadIdx.x; j < TPB * 9 / 4; j += TPB)
        o4[j] = s4[j];
}

extern "C" void kernel_launch(void* const* d_in, const int* in_sizes, int n_in,
                              void* d_out, int out_size) {
    const float4* quat = (const float4*)d_in[0];  // [N,4] float32
    const float*  ls   = (const float*)d_in[1];   // [N,3] float32
    float*        out  = (float*)d_out;           // [N,3,3] float32

    const int n = in_sizes[0] / 4;                // 4,000,000 (divisible by 256)
    cov_kernel<<<n / TPB, TPB>>>(quat, ls, out);
}